// round 11
// baseline (speedup 1.0000x reference)
#include <cuda_runtime.h>
#include <cuda_fp16.h>
#include <cstdint>

#define N_NODES 50000
#define D 256
#define E_MAX 800000

// ---------------- scratch (static device globals; no allocation) ----------------
__device__ int   g_deg[N_NODES];
__device__ int   g_rowptr[N_NODES + 1];
__device__ int   g_cursor[N_NODES];
__device__ int   g_eidx[E_MAX];
// current-layer features as fp16 pairs: [row][t(128)] u32 (2 halves along feature dim)
__device__ __align__(16) uint32_t g_feat[(size_t)N_NODES * 128];
// A = [mean | self] fp16 pairs: 256 u32/row
__device__ __align__(16) uint32_t g_Ahi[(size_t)N_NODES * 256];
// B^T = [Wl;Wr]^T per layer: [layer][n(256)][k2(256)] u32, hi + residual lo
__device__ __align__(16) uint32_t g_Bt_hi[2 * 256 * 256];
__device__ __align__(16) uint32_t g_Bt_lo[2 * 256 * 256];

// ---------------- small helpers ----------------
__device__ __forceinline__ uint32_t smem_to_u32(const void* p) {
    uint32_t a;
    asm("{ .reg .u64 t; cvta.to.shared.u64 t, %1; cvt.u32.u64 %0, t; }" : "=r"(a) : "l"(p));
    return a;
}

__device__ __forceinline__ uint32_t pack_h2(__half a, __half b) {
    __half2 h = __halves2half2(a, b);
    return *reinterpret_cast<uint32_t*>(&h);
}

__device__ __forceinline__ uint32_t pack_f2h2(float a, float b) {
    return pack_h2(__float2half_rn(a), __float2half_rn(b));
}

__device__ __forceinline__ void cvt_hilo2(float a, float b, uint32_t& hi, uint32_t& lo) {
    __half ha = __float2half_rn(a);
    __half hb = __float2half_rn(b);
    __half la = __float2half_rn(a - __half2float(ha));
    __half lb = __float2half_rn(b - __half2float(hb));
    hi = pack_h2(ha, hb);
    lo = pack_h2(la, lb);
}

#define CP_ASYNC16(dst, src, sz) \
    asm volatile("cp.async.cg.shared.global [%0], [%1], 16, %2;" \
        :: "r"(dst), "l"(src), "r"(sz) : "memory")
#define CP_COMMIT() asm volatile("cp.async.commit_group;" ::: "memory")
#define CP_WAIT1() asm volatile("cp.async.wait_group 1;" ::: "memory")
#define CP_WAIT0() asm volatile("cp.async.wait_group 0;" ::: "memory")

#define LDSM_X4(r0, r1, r2, r3, addr) \
    asm volatile("ldmatrix.sync.aligned.m8n8.x4.shared.b16 {%0,%1,%2,%3}, [%4];" \
        : "=r"(r0), "=r"(r1), "=r"(r2), "=r"(r3) : "r"(addr))
#define LDSM_X2(r0, r1, addr) \
    asm volatile("ldmatrix.sync.aligned.m8n8.x2.shared.b16 {%0,%1}, [%2];" \
        : "=r"(r0), "=r"(r1) : "r"(addr))

__device__ __forceinline__ void mma_f32acc(float* c, const uint32_t* a, uint32_t b0, uint32_t b1) {
    asm volatile(
        "mma.sync.aligned.m16n8k16.row.col.f32.f16.f16.f32 "
        "{%0,%1,%2,%3}, {%4,%5,%6,%7}, {%8,%9}, {%0,%1,%2,%3};\n"
        : "+f"(c[0]), "+f"(c[1]), "+f"(c[2]), "+f"(c[3])
        : "r"(a[0]), "r"(a[1]), "r"(a[2]), "r"(a[3]), "r"(b0), "r"(b1));
}

// ---------------- prep: degree count + x -> fp16 feature array (fused) ----------
__global__ void prep_kernel(const int* __restrict__ ei, const float* __restrict__ x,
                            int E, int nb_count) {
    int b = blockIdx.x;
    if (b < nb_count) {
        int e = b * 256 + threadIdx.x;
        if (e < E) atomicAdd(&g_deg[ei[E + e]], 1);
    } else {
        int idx = (b - nb_count) * 256 + threadIdx.x;   // 0 .. N_NODES*128-1
        if (idx < N_NODES * 128) {
            float2 v = *(const float2*)&x[(size_t)idx * 2];
            g_feat[idx] = pack_f2h2(v.x, v.y);
        }
    }
}

// single-block full scan: rowptr/cursor from deg; re-zeros deg for the next replay
#define SCAN_PER_T 49
__global__ void scanall_kernel(int E) {
    __shared__ int ssum[1024];
    int t = threadIdx.x;
    int base = t * SCAN_PER_T;
    int s = 0;
#pragma unroll 7
    for (int i = 0; i < SCAN_PER_T; i++) {
        int idx = base + i;
        int v = (idx < N_NODES) ? g_deg[idx] : 0;
        if (idx < N_NODES) g_rowptr[idx] = s;
        s += v;
    }
    ssum[t] = s;
    __syncthreads();
    for (int off = 1; off < 1024; off <<= 1) {
        int v = (t >= off) ? ssum[t - off] : 0;
        __syncthreads();
        ssum[t] += v;
        __syncthreads();
    }
    int tbase = ssum[t] - s;
#pragma unroll 7
    for (int i = 0; i < SCAN_PER_T; i++) {
        int idx = base + i;
        if (idx < N_NODES) {
            int r = g_rowptr[idx] + tbase;
            g_rowptr[idx] = r;
            g_cursor[idx] = r;
            g_deg[idx]    = 0;
        }
    }
    if (t == 0) g_rowptr[N_NODES] = E;
}

__global__ void scatter_kernel(const int* __restrict__ ei, int E) {
    int e = blockIdx.x * blockDim.x + threadIdx.x;
    if (e < E) {
        int src = ei[e];
        int dst = ei[E + e];
        int pos = atomicAdd(&g_cursor[dst], 1);
        g_eidx[pos] = src;
    }
}

// ---------------- mean aggregation over fp16 features -> A tile ----------------
// gathers fp16 pairs (512B/edge), f32 accumulation; fills both halves of g_Ahi
__global__ void aggregate_kernel() {
    int row = blockIdx.x;
    int t   = threadIdx.x;       // 0..127
    int start = g_rowptr[row];
    int end   = g_rowptr[row + 1];
    float a0 = 0.f, a1 = 0.f;
    int e = start;
    for (; e + 4 <= end; e += 4) {
        int s0 = g_eidx[e], s1 = g_eidx[e + 1], s2 = g_eidx[e + 2], s3 = g_eidx[e + 3];
        uint32_t u0 = g_feat[(size_t)s0 * 128 + t];
        uint32_t u1 = g_feat[(size_t)s1 * 128 + t];
        uint32_t u2 = g_feat[(size_t)s2 * 128 + t];
        uint32_t u3 = g_feat[(size_t)s3 * 128 + t];
        float2 f0 = __half22float2(*reinterpret_cast<__half2*>(&u0));
        float2 f1 = __half22float2(*reinterpret_cast<__half2*>(&u1));
        float2 f2 = __half22float2(*reinterpret_cast<__half2*>(&u2));
        float2 f3 = __half22float2(*reinterpret_cast<__half2*>(&u3));
        a0 += (f0.x + f1.x) + (f2.x + f3.x);
        a1 += (f0.y + f1.y) + (f2.y + f3.y);
    }
    for (; e < end; e++) {
        uint32_t u = g_feat[(size_t)g_eidx[e] * 128 + t];
        float2 f = __half22float2(*reinterpret_cast<__half2*>(&u));
        a0 += f.x; a1 += f.y;
    }
    int deg = end - start;
    float scale = (deg > 0) ? 1.f / (float)deg : 0.f;
    g_Ahi[(size_t)row * 256 + t]       = pack_f2h2(a0 * scale, a1 * scale);
    g_Ahi[(size_t)row * 256 + 128 + t] = g_feat[(size_t)row * 128 + t];
}

// ---------------- W -> B^T fp16 hi/lo convert (once) ----------------
__global__ void convert_w_kernel(const float* __restrict__ W1l, const float* __restrict__ W1r,
                                 const float* __restrict__ W2l, const float* __restrict__ W2r) {
    int idx = blockIdx.x * 256 + threadIdx.x;        // 0..131071
    int layer = idx >> 16;
    int n  = (idx >> 8) & 255;
    int k2 = idx & 255;
    int k  = k2 * 2;
    const float* Wl = layer ? W2l : W1l;
    const float* Wr = layer ? W2r : W1r;
    float v0, v1;
    if (k < 256) { v0 = Wl[k * 256 + n]; v1 = Wl[(k + 1) * 256 + n]; }
    else         { v0 = Wr[(k - 256) * 256 + n]; v1 = Wr[(k - 255) * 256 + n]; }
    uint32_t hi, lo;
    cvt_hilo2(v0, v1, hi, lo);
    g_Bt_hi[idx] = hi;
    g_Bt_lo[idx] = lo;
}

// ---------------- fp16 mma.sync GEMM: A @ (B_hi + B_lo) ----------------
// OUT_FP16: write relu(result) as fp16 pairs into g_feat (layer 1)
// else:     write f32 result + bias to out_param (layer 2)
#define ROWB 80
#define TILE_BYTES (128 * ROWB)
#define STAGE_BYTES (3 * TILE_BYTES)   // A, Bhi, Blo
#define SM_DYN (2 * STAGE_BYTES)       // 61440

template <bool RELU, bool OUT_FP16>
__global__ __launch_bounds__(256, 2) void gemm_f16_kernel(
    int layer, const float* __restrict__ bias, float* __restrict__ out_param)
{
    extern __shared__ char dsm[];
    __shared__ float bias_s[128];

    const uint32_t* __restrict__ BtH = g_Bt_hi + (size_t)layer * 65536;
    const uint32_t* __restrict__ BtL = g_Bt_lo + (size_t)layer * 65536;

    int tid  = threadIdx.x;
    int wid  = tid >> 5;
    int lid  = tid & 31;
    int g    = lid >> 2;
    int tg   = lid & 3;
    int row0 = blockIdx.x * 128;
    int n0   = blockIdx.y * 128;

    int warp_m = (wid & 1) * 64;
    int warp_n = (wid >> 1) * 32;

    if (tid < 128) bias_s[tid] = bias[n0 + tid];

    uint32_t s_base = smem_to_u32(dsm);

    uint32_t a_lane_off = (uint32_t)(((lid & 7) + ((lid >> 3) & 1) * 8) * ROWB + (lid >> 4) * 16);
    uint32_t b_lane_off = (uint32_t)((lid & 7) * ROWB + (((lid & 15) >> 3)) * 16);

    float acc[4][4][4];
#pragma unroll
    for (int mi = 0; mi < 4; mi++)
#pragma unroll
        for (int ni = 0; ni < 4; ni++)
#pragma unroll
            for (int r = 0; r < 4; r++) acc[mi][ni][r] = 0.f;

    int lrow = tid >> 1;
    int lseg = (tid & 1) * 32;
    int gr   = row0 + lrow;
    int a_sz = (gr < N_NODES) ? 16 : 0;
    int gra  = (gr < N_NODES) ? gr : (N_NODES - 1);
    const char* aHs = (const char*)(g_Ahi + (size_t)gra * 256) + lseg;
    const char* bHs = (const char*)(BtH + (size_t)(n0 + lrow) * 256) + lseg;
    const char* bLs = (const char*)(BtL + (size_t)(n0 + lrow) * 256) + lseg;
    uint32_t dst_row = lrow * ROWB + lseg;

    auto tile_load = [&](int kt, int stage) {
        uint32_t st = s_base + stage * STAGE_BYTES;
        const char* srcA    = aHs + kt * 64;
        const char* srcB_hi = bHs + kt * 64;
        const char* srcB_lo = bLs + kt * 64;
        uint32_t d0 = st + dst_row;
        CP_ASYNC16(d0,                  srcA,         a_sz);
        CP_ASYNC16(d0 + 16,             srcA + 16,    a_sz);
        CP_ASYNC16(d0 + TILE_BYTES,     srcB_hi,      16);
        CP_ASYNC16(d0 + TILE_BYTES + 16,srcB_hi + 16, 16);
        CP_ASYNC16(d0 + 2 * TILE_BYTES,     srcB_lo,      16);
        CP_ASYNC16(d0 + 2 * TILE_BYTES + 16,srcB_lo + 16, 16);
    };

    tile_load(0, 0);
    CP_COMMIT();

    for (int kt = 0; kt < 16; kt++) {
        int st = kt & 1;
        if (kt + 1 < 16) { tile_load(kt + 1, st ^ 1); CP_COMMIT(); CP_WAIT1(); }
        else             { CP_WAIT0(); }
        __syncthreads();

        uint32_t sa   = s_base + st * STAGE_BYTES;
        uint32_t sb_h = sa + TILE_BYTES;
        uint32_t sb_l = sa + 2 * TILE_BYTES;

#pragma unroll
        for (int ks = 0; ks < 2; ks++) {
            uint32_t koff = ks * 32;
            uint32_t bh[4][2], bl[4][2];
#pragma unroll
            for (int ni = 0; ni < 4; ni++) {
                uint32_t nbase = (uint32_t)((warp_n + ni * 8) * ROWB) + koff;
                LDSM_X2(bh[ni][0], bh[ni][1], sb_h + nbase + b_lane_off);
                LDSM_X2(bl[ni][0], bl[ni][1], sb_l + nbase + b_lane_off);
            }
#pragma unroll
            for (int mi = 0; mi < 4; mi++) {
                uint32_t mbase = (uint32_t)((warp_m + mi * 16) * ROWB) + koff;
                uint32_t ah[4];
                LDSM_X4(ah[0], ah[1], ah[2], ah[3], sa + mbase + a_lane_off);
#pragma unroll
                for (int ni = 0; ni < 4; ni++) mma_f32acc(acc[mi][ni], ah, bh[ni][0], bh[ni][1]);
#pragma unroll
                for (int ni = 0; ni < 4; ni++) mma_f32acc(acc[mi][ni], ah, bl[ni][0], bl[ni][1]);
            }
        }
        __syncthreads();
    }

    // epilogue
#pragma unroll
    for (int mi = 0; mi < 4; mi++) {
#pragma unroll
        for (int ni = 0; ni < 4; ni++) {
            int lc = warp_n + ni * 8 + tg * 2;
            float bx = bias_s[lc], by = bias_s[lc + 1];
            int gc  = n0 + lc;
            int gr0 = row0 + warp_m + mi * 16 + g;
            int gr1 = gr0 + 8;
            float2 v0, v1;
            v0.x = acc[mi][ni][0] + bx; v0.y = acc[mi][ni][1] + by;
            v1.x = acc[mi][ni][2] + bx; v1.y = acc[mi][ni][3] + by;
            if (RELU) {
                v0.x = fmaxf(v0.x, 0.f); v0.y = fmaxf(v0.y, 0.f);
                v1.x = fmaxf(v1.x, 0.f); v1.y = fmaxf(v1.y, 0.f);
            }
            if (OUT_FP16) {
                if (gr0 < N_NODES) g_feat[(size_t)gr0 * 128 + (gc >> 1)] = pack_f2h2(v0.x, v0.y);
                if (gr1 < N_NODES) g_feat[(size_t)gr1 * 128 + (gc >> 1)] = pack_f2h2(v1.x, v1.y);
            } else {
                if (gr0 < N_NODES) *(float2*)&out_param[(size_t)gr0 * D + gc] = v0;
                if (gr1 < N_NODES) *(float2*)&out_param[(size_t)gr1 * D + gc] = v1;
            }
        }
    }
}

// ---------------- launch ----------------
extern "C" void kernel_launch(void* const* d_in, const int* in_sizes, int n_in,
                              void* d_out, int out_size)
{
    const float* x   = (const float*)d_in[0];
    const int*   ei  = (const int*)d_in[1];     // JAX randint -> int32 (x64 disabled)
    const float* W1l = (const float*)d_in[2];
    const float* b1  = (const float*)d_in[3];
    const float* W1r = (const float*)d_in[4];
    const float* W2l = (const float*)d_in[5];
    const float* b2  = (const float*)d_in[6];
    const float* W2r = (const float*)d_in[7];
    float*       out = (float*)d_out;

    int E = in_sizes[1] / 2;
    if (E > E_MAX) E = E_MAX;

    cudaFuncSetAttribute(gemm_f16_kernel<true, true>,
                         cudaFuncAttributeMaxDynamicSharedMemorySize, SM_DYN);
    cudaFuncSetAttribute(gemm_f16_kernel<false, false>,
                         cudaFuncAttributeMaxDynamicSharedMemorySize, SM_DYN);

    int nb_count = (E + 255) / 256;
    int nb_conv  = (N_NODES * 128 + 255) / 256;

    // 0: degree count + x->fp16 (fused)
    prep_kernel<<<nb_count + nb_conv, 256>>>(ei, x, E, nb_count);
    // 1: scan (also re-zeros deg for next replay)
    scanall_kernel<<<1, 1024>>>(E);
    // 2: CSR scatter
    scatter_kernel<<<nb_count, 256>>>(ei, E);
    // 3: layer-1 aggregation (profiled slot)
    aggregate_kernel<<<N_NODES, 128>>>();
    // 4: weight conversion
    convert_w_kernel<<<512, 256>>>(W1l, W1r, W2l, W2r);

    dim3 ggrid((N_NODES + 127) / 128, 2);
    // 5: layer-1 GEMM -> g_feat (fp16 relu h)
    gemm_f16_kernel<true, true><<<ggrid, 256, SM_DYN>>>(0, b1, nullptr);
    // 6: layer-2 aggregation
    aggregate_kernel<<<N_NODES, 128>>>();
    // 7: layer-2 GEMM -> out (f32)
    gemm_f16_kernel<false, false><<<ggrid, 256, SM_DYN>>>(1, b2, out);
}

// round 12
// speedup vs baseline: 1.2051x; 1.2051x over previous
#include <cuda_runtime.h>
#include <cuda_fp16.h>
#include <cstdint>

#define N_NODES 50000
#define D 256
#define E_MAX 800000

// ---------------- scratch (static device globals; no allocation) ----------------
__device__ int   g_deg[N_NODES];
__device__ int   g_rowptr[N_NODES + 1];
__device__ int   g_cursor[N_NODES];
__device__ int   g_eidx[E_MAX];
// current-layer features as fp16 pairs: [row][t(128)] u32 (2 halves along feature dim)
__device__ __align__(16) uint32_t g_feat[(size_t)N_NODES * 128];
// A = [mean | self] fp16 pairs: 256 u32/row
__device__ __align__(16) uint32_t g_Ahi[(size_t)N_NODES * 256];
// B^T = [Wl;Wr]^T per layer: [layer][n(256)][k2(256)] u32, hi + residual lo
__device__ __align__(16) uint32_t g_Bt_hi[2 * 256 * 256];
__device__ __align__(16) uint32_t g_Bt_lo[2 * 256 * 256];

// ---------------- small helpers ----------------
__device__ __forceinline__ uint32_t smem_to_u32(const void* p) {
    uint32_t a;
    asm("{ .reg .u64 t; cvta.to.shared.u64 t, %1; cvt.u32.u64 %0, t; }" : "=r"(a) : "l"(p));
    return a;
}

__device__ __forceinline__ uint32_t pack_h2(__half a, __half b) {
    __half2 h = __halves2half2(a, b);
    return *reinterpret_cast<uint32_t*>(&h);
}

__device__ __forceinline__ uint32_t pack_f2h2(float a, float b) {
    return pack_h2(__float2half_rn(a), __float2half_rn(b));
}

__device__ __forceinline__ void cvt_hilo2(float a, float b, uint32_t& hi, uint32_t& lo) {
    __half ha = __float2half_rn(a);
    __half hb = __float2half_rn(b);
    __half la = __float2half_rn(a - __half2float(ha));
    __half lb = __float2half_rn(b - __half2float(hb));
    hi = pack_h2(ha, hb);
    lo = pack_h2(la, lb);
}

__device__ __forceinline__ void acc_u4(float* a, uint4 u) {
    float2 f0 = __half22float2(*reinterpret_cast<__half2*>(&u.x));
    float2 f1 = __half22float2(*reinterpret_cast<__half2*>(&u.y));
    float2 f2 = __half22float2(*reinterpret_cast<__half2*>(&u.z));
    float2 f3 = __half22float2(*reinterpret_cast<__half2*>(&u.w));
    a[0] += f0.x; a[1] += f0.y; a[2] += f1.x; a[3] += f1.y;
    a[4] += f2.x; a[5] += f2.y; a[6] += f3.x; a[7] += f3.y;
}

#define CP_ASYNC16(dst, src, sz) \
    asm volatile("cp.async.cg.shared.global [%0], [%1], 16, %2;" \
        :: "r"(dst), "l"(src), "r"(sz) : "memory")
#define CP_COMMIT() asm volatile("cp.async.commit_group;" ::: "memory")
#define CP_WAIT1() asm volatile("cp.async.wait_group 1;" ::: "memory")
#define CP_WAIT0() asm volatile("cp.async.wait_group 0;" ::: "memory")

#define LDSM_X4(r0, r1, r2, r3, addr) \
    asm volatile("ldmatrix.sync.aligned.m8n8.x4.shared.b16 {%0,%1,%2,%3}, [%4];" \
        : "=r"(r0), "=r"(r1), "=r"(r2), "=r"(r3) : "r"(addr))
#define LDSM_X2(r0, r1, addr) \
    asm volatile("ldmatrix.sync.aligned.m8n8.x2.shared.b16 {%0,%1}, [%2];" \
        : "=r"(r0), "=r"(r1) : "r"(addr))

__device__ __forceinline__ void mma_f32acc(float* c, const uint32_t* a, uint32_t b0, uint32_t b1) {
    asm volatile(
        "mma.sync.aligned.m16n8k16.row.col.f32.f16.f16.f32 "
        "{%0,%1,%2,%3}, {%4,%5,%6,%7}, {%8,%9}, {%0,%1,%2,%3};\n"
        : "+f"(c[0]), "+f"(c[1]), "+f"(c[2]), "+f"(c[3])
        : "r"(a[0]), "r"(a[1]), "r"(a[2]), "r"(a[3]), "r"(b0), "r"(b1));
}

// ------ prep: degree count + x->fp16 + W->B^T hi/lo (all fused, disjoint blocks) ------
__global__ void prep_kernel(const int* __restrict__ ei, const float* __restrict__ x,
                            const float* __restrict__ W1l, const float* __restrict__ W1r,
                            const float* __restrict__ W2l, const float* __restrict__ W2r,
                            int E, int nb_count, int nb_conv) {
    int b = blockIdx.x;
    if (b < nb_count) {
        int e = b * 256 + threadIdx.x;
        if (e < E) atomicAdd(&g_deg[ei[E + e]], 1);
    } else if (b < nb_count + nb_conv) {
        int idx = (b - nb_count) * 256 + threadIdx.x;   // 0 .. N_NODES*128-1
        if (idx < N_NODES * 128) {
            float2 v = *(const float2*)&x[(size_t)idx * 2];
            g_feat[idx] = pack_f2h2(v.x, v.y);
        }
    } else {
        int idx = (b - nb_count - nb_conv) * 256 + threadIdx.x;  // 0..131071
        int layer = idx >> 16;
        int n  = (idx >> 8) & 255;
        int k2 = idx & 255;
        int k  = k2 * 2;
        const float* Wl = layer ? W2l : W1l;
        const float* Wr = layer ? W2r : W1r;
        float v0, v1;
        if (k < 256) { v0 = Wl[k * 256 + n]; v1 = Wl[(k + 1) * 256 + n]; }
        else         { v0 = Wr[(k - 256) * 256 + n]; v1 = Wr[(k - 255) * 256 + n]; }
        uint32_t hi, lo;
        cvt_hilo2(v0, v1, hi, lo);
        g_Bt_hi[idx] = hi;
        g_Bt_lo[idx] = lo;
    }
}

// single-block full scan: rowptr/cursor from deg; re-zeros deg for the next replay
#define SCAN_PER_T 49
__global__ void scanall_kernel(int E) {
    __shared__ int ssum[1024];
    int t = threadIdx.x;
    int base = t * SCAN_PER_T;
    int s = 0;
#pragma unroll 7
    for (int i = 0; i < SCAN_PER_T; i++) {
        int idx = base + i;
        int v = (idx < N_NODES) ? g_deg[idx] : 0;
        if (idx < N_NODES) g_rowptr[idx] = s;
        s += v;
    }
    ssum[t] = s;
    __syncthreads();
    for (int off = 1; off < 1024; off <<= 1) {
        int v = (t >= off) ? ssum[t - off] : 0;
        __syncthreads();
        ssum[t] += v;
        __syncthreads();
    }
    int tbase = ssum[t] - s;
#pragma unroll 7
    for (int i = 0; i < SCAN_PER_T; i++) {
        int idx = base + i;
        if (idx < N_NODES) {
            int r = g_rowptr[idx] + tbase;
            g_rowptr[idx] = r;
            g_cursor[idx] = r;
            g_deg[idx]    = 0;
        }
    }
    if (t == 0) g_rowptr[N_NODES] = E;
}

__global__ void scatter_kernel(const int* __restrict__ ei, int E) {
    int e = blockIdx.x * blockDim.x + threadIdx.x;
    if (e < E) {
        int src = ei[e];
        int dst = ei[E + e];
        int pos = atomicAdd(&g_cursor[dst], 1);
        g_eidx[pos] = src;
    }
}

// ---------------- mean aggregation: warp per row, uint4 gathers ----------------
// lane handles 8 features (16B); warp covers the full 256-feature row.
__global__ void aggregate_kernel() {
    int w    = threadIdx.x >> 5;
    int lane = threadIdx.x & 31;
    int row  = blockIdx.x * 4 + w;
    const uint4* __restrict__ feat4 = (const uint4*)g_feat;   // 32 uint4 per row

    int start = g_rowptr[row];
    int end   = g_rowptr[row + 1];

    float acc[8];
#pragma unroll
    for (int i = 0; i < 8; i++) acc[i] = 0.f;

    int e = start;
    for (; e + 2 <= end; e += 2) {
        int s0 = g_eidx[e];
        int s1 = g_eidx[e + 1];
        uint4 u0 = feat4[s0 * 32 + lane];
        uint4 u1 = feat4[s1 * 32 + lane];
        acc_u4(acc, u0);
        acc_u4(acc, u1);
    }
    if (e < end) {
        uint4 u = feat4[g_eidx[e] * 32 + lane];
        acc_u4(acc, u);
    }

    int deg = end - start;
    float scale = (deg > 0) ? 1.f / (float)deg : 0.f;
    uint4 o;
    o.x = pack_f2h2(acc[0] * scale, acc[1] * scale);
    o.y = pack_f2h2(acc[2] * scale, acc[3] * scale);
    o.z = pack_f2h2(acc[4] * scale, acc[5] * scale);
    o.w = pack_f2h2(acc[6] * scale, acc[7] * scale);
    uint4* A4 = (uint4*)g_Ahi;                 // 64 uint4 per row
    A4[row * 64 + lane]      = o;              // mean half
    A4[row * 64 + 32 + lane] = feat4[row * 32 + lane];   // self half
}

// ---------------- fp16 mma.sync GEMM: A @ (B_hi + B_lo) ----------------
#define ROWB 80
#define TILE_BYTES (128 * ROWB)
#define STAGE_BYTES (3 * TILE_BYTES)   // A, Bhi, Blo
#define SM_DYN (2 * STAGE_BYTES)       // 61440

template <bool RELU, bool OUT_FP16>
__global__ __launch_bounds__(256, 2) void gemm_f16_kernel(
    int layer, const float* __restrict__ bias, float* __restrict__ out_param)
{
    extern __shared__ char dsm[];
    __shared__ float bias_s[128];

    const uint32_t* __restrict__ BtH = g_Bt_hi + (size_t)layer * 65536;
    const uint32_t* __restrict__ BtL = g_Bt_lo + (size_t)layer * 65536;

    int tid  = threadIdx.x;
    int wid  = tid >> 5;
    int lid  = tid & 31;
    int g    = lid >> 2;
    int tg   = lid & 3;
    int row0 = blockIdx.x * 128;
    int n0   = blockIdx.y * 128;

    int warp_m = (wid & 1) * 64;
    int warp_n = (wid >> 1) * 32;

    if (tid < 128) bias_s[tid] = bias[n0 + tid];

    uint32_t s_base = smem_to_u32(dsm);

    uint32_t a_lane_off = (uint32_t)(((lid & 7) + ((lid >> 3) & 1) * 8) * ROWB + (lid >> 4) * 16);
    uint32_t b_lane_off = (uint32_t)((lid & 7) * ROWB + (((lid & 15) >> 3)) * 16);

    float acc[4][4][4];
#pragma unroll
    for (int mi = 0; mi < 4; mi++)
#pragma unroll
        for (int ni = 0; ni < 4; ni++)
#pragma unroll
            for (int r = 0; r < 4; r++) acc[mi][ni][r] = 0.f;

    int lrow = tid >> 1;
    int lseg = (tid & 1) * 32;
    int gr   = row0 + lrow;
    int a_sz = (gr < N_NODES) ? 16 : 0;
    int gra  = (gr < N_NODES) ? gr : (N_NODES - 1);
    const char* aHs = (const char*)(g_Ahi + (size_t)gra * 256) + lseg;
    const char* bHs = (const char*)(BtH + (size_t)(n0 + lrow) * 256) + lseg;
    const char* bLs = (const char*)(BtL + (size_t)(n0 + lrow) * 256) + lseg;
    uint32_t dst_row = lrow * ROWB + lseg;

    auto tile_load = [&](int kt, int stage) {
        uint32_t st = s_base + stage * STAGE_BYTES;
        const char* srcA    = aHs + kt * 64;
        const char* srcB_hi = bHs + kt * 64;
        const char* srcB_lo = bLs + kt * 64;
        uint32_t d0 = st + dst_row;
        CP_ASYNC16(d0,                  srcA,         a_sz);
        CP_ASYNC16(d0 + 16,             srcA + 16,    a_sz);
        CP_ASYNC16(d0 + TILE_BYTES,     srcB_hi,      16);
        CP_ASYNC16(d0 + TILE_BYTES + 16,srcB_hi + 16, 16);
        CP_ASYNC16(d0 + 2 * TILE_BYTES,     srcB_lo,      16);
        CP_ASYNC16(d0 + 2 * TILE_BYTES + 16,srcB_lo + 16, 16);
    };

    tile_load(0, 0);
    CP_COMMIT();

    for (int kt = 0; kt < 16; kt++) {
        int st = kt & 1;
        if (kt + 1 < 16) { tile_load(kt + 1, st ^ 1); CP_COMMIT(); CP_WAIT1(); }
        else             { CP_WAIT0(); }
        __syncthreads();

        uint32_t sa   = s_base + st * STAGE_BYTES;
        uint32_t sb_h = sa + TILE_BYTES;
        uint32_t sb_l = sa + 2 * TILE_BYTES;

#pragma unroll
        for (int ks = 0; ks < 2; ks++) {
            uint32_t koff = ks * 32;
            uint32_t bh[4][2], bl[4][2];
#pragma unroll
            for (int ni = 0; ni < 4; ni++) {
                uint32_t nbase = (uint32_t)((warp_n + ni * 8) * ROWB) + koff;
                LDSM_X2(bh[ni][0], bh[ni][1], sb_h + nbase + b_lane_off);
                LDSM_X2(bl[ni][0], bl[ni][1], sb_l + nbase + b_lane_off);
            }
#pragma unroll
            for (int mi = 0; mi < 4; mi++) {
                uint32_t mbase = (uint32_t)((warp_m + mi * 16) * ROWB) + koff;
                uint32_t ah[4];
                LDSM_X4(ah[0], ah[1], ah[2], ah[3], sa + mbase + a_lane_off);
#pragma unroll
                for (int ni = 0; ni < 4; ni++) mma_f32acc(acc[mi][ni], ah, bh[ni][0], bh[ni][1]);
#pragma unroll
                for (int ni = 0; ni < 4; ni++) mma_f32acc(acc[mi][ni], ah, bl[ni][0], bl[ni][1]);
            }
        }
        __syncthreads();
    }

    // epilogue
#pragma unroll
    for (int mi = 0; mi < 4; mi++) {
#pragma unroll
        for (int ni = 0; ni < 4; ni++) {
            int lc = warp_n + ni * 8 + tg * 2;
            float bx = bias_s[lc], by = bias_s[lc + 1];
            int gc  = n0 + lc;
            int gr0 = row0 + warp_m + mi * 16 + g;
            int gr1 = gr0 + 8;
            float2 v0, v1;
            v0.x = acc[mi][ni][0] + bx; v0.y = acc[mi][ni][1] + by;
            v1.x = acc[mi][ni][2] + bx; v1.y = acc[mi][ni][3] + by;
            if (RELU) {
                v0.x = fmaxf(v0.x, 0.f); v0.y = fmaxf(v0.y, 0.f);
                v1.x = fmaxf(v1.x, 0.f); v1.y = fmaxf(v1.y, 0.f);
            }
            if (OUT_FP16) {
                if (gr0 < N_NODES) g_feat[(size_t)gr0 * 128 + (gc >> 1)] = pack_f2h2(v0.x, v0.y);
                if (gr1 < N_NODES) g_feat[(size_t)gr1 * 128 + (gc >> 1)] = pack_f2h2(v1.x, v1.y);
            } else {
                if (gr0 < N_NODES) *(float2*)&out_param[(size_t)gr0 * D + gc] = v0;
                if (gr1 < N_NODES) *(float2*)&out_param[(size_t)gr1 * D + gc] = v1;
            }
        }
    }
}

// ---------------- launch ----------------
extern "C" void kernel_launch(void* const* d_in, const int* in_sizes, int n_in,
                              void* d_out, int out_size)
{
    const float* x   = (const float*)d_in[0];
    const int*   ei  = (const int*)d_in[1];     // JAX randint -> int32 (x64 disabled)
    const float* W1l = (const float*)d_in[2];
    const float* b1  = (const float*)d_in[3];
    const float* W1r = (const float*)d_in[4];
    const float* W2l = (const float*)d_in[5];
    const float* b2  = (const float*)d_in[6];
    const float* W2r = (const float*)d_in[7];
    float*       out = (float*)d_out;

    int E = in_sizes[1] / 2;
    if (E > E_MAX) E = E_MAX;

    cudaFuncSetAttribute(gemm_f16_kernel<true, true>,
                         cudaFuncAttributeMaxDynamicSharedMemorySize, SM_DYN);
    cudaFuncSetAttribute(gemm_f16_kernel<false, false>,
                         cudaFuncAttributeMaxDynamicSharedMemorySize, SM_DYN);

    int nb_count = (E + 255) / 256;
    int nb_conv  = (N_NODES * 128 + 255) / 256;
    int nb_w     = 512;

    // 0: degree count + x->fp16 + W convert (fused)
    prep_kernel<<<nb_count + nb_conv + nb_w, 256>>>(ei, x, W1l, W1r, W2l, W2r,
                                                    E, nb_count, nb_conv);
    // 1: scan (re-zeros deg for next replay)
    scanall_kernel<<<1, 1024>>>(E);
    // 2: CSR scatter
    scatter_kernel<<<nb_count, 256>>>(ei, E);
    // 3: layer-1 aggregation (profiled slot)
    aggregate_kernel<<<N_NODES / 4, 128>>>();

    dim3 ggrid((N_NODES + 127) / 128, 2);
    // 4: layer-1 GEMM -> g_feat (fp16 relu h)
    gemm_f16_kernel<true, true><<<ggrid, 256, SM_DYN>>>(0, b1, nullptr);
    // 5: layer-2 aggregation
    aggregate_kernel<<<N_NODES / 4, 128>>>();
    // 6: layer-2 GEMM -> out (f32)
    gemm_f16_kernel<false, false><<<ggrid, 256, SM_DYN>>>(1, b2, out);
}

// round 13
// speedup vs baseline: 1.4298x; 1.1864x over previous
#include <cuda_runtime.h>
#include <cuda_fp16.h>
#include <cstdint>

#define N_NODES 50000
#define D 256
#define E_MAX 800000

// ---------------- scratch (static device globals; no allocation) ----------------
__device__ int   g_deg[N_NODES];
__device__ int   g_rowptr[N_NODES + 1];
__device__ int   g_cursor[N_NODES];
__device__ int   g_eidx[E_MAX];
// current-layer features as fp16 pairs: [row][t(128)] u32
__device__ __align__(16) uint32_t g_feat[(size_t)N_NODES * 128];
// A = [mean | self] fp16 pairs: 256 u32/row
__device__ __align__(16) uint32_t g_Ahi[(size_t)N_NODES * 256];
// B^T = [Wl;Wr]^T per layer, single fp16: [layer][n(256)][k2(256)] u32
__device__ __align__(16) uint32_t g_Bt[2 * 256 * 256];

// ---------------- small helpers ----------------
__device__ __forceinline__ uint32_t smem_to_u32(const void* p) {
    uint32_t a;
    asm("{ .reg .u64 t; cvta.to.shared.u64 t, %1; cvt.u32.u64 %0, t; }" : "=r"(a) : "l"(p));
    return a;
}

__device__ __forceinline__ uint32_t pack_h2(__half a, __half b) {
    __half2 h = __halves2half2(a, b);
    return *reinterpret_cast<uint32_t*>(&h);
}

__device__ __forceinline__ uint32_t pack_f2h2(float a, float b) {
    return pack_h2(__float2half_rn(a), __float2half_rn(b));
}

__device__ __forceinline__ void acc_u4(float* a, uint4 u) {
    float2 f0 = __half22float2(*reinterpret_cast<__half2*>(&u.x));
    float2 f1 = __half22float2(*reinterpret_cast<__half2*>(&u.y));
    float2 f2 = __half22float2(*reinterpret_cast<__half2*>(&u.z));
    float2 f3 = __half22float2(*reinterpret_cast<__half2*>(&u.w));
    a[0] += f0.x; a[1] += f0.y; a[2] += f1.x; a[3] += f1.y;
    a[4] += f2.x; a[5] += f2.y; a[6] += f3.x; a[7] += f3.y;
}

#define CP_ASYNC16(dst, src, sz) \
    asm volatile("cp.async.cg.shared.global [%0], [%1], 16, %2;" \
        :: "r"(dst), "l"(src), "r"(sz) : "memory")
#define CP_COMMIT() asm volatile("cp.async.commit_group;" ::: "memory")
#define CP_WAIT1() asm volatile("cp.async.wait_group 1;" ::: "memory")
#define CP_WAIT0() asm volatile("cp.async.wait_group 0;" ::: "memory")

#define LDSM_X4(r0, r1, r2, r3, addr) \
    asm volatile("ldmatrix.sync.aligned.m8n8.x4.shared.b16 {%0,%1,%2,%3}, [%4];" \
        : "=r"(r0), "=r"(r1), "=r"(r2), "=r"(r3) : "r"(addr))
#define LDSM_X2(r0, r1, addr) \
    asm volatile("ldmatrix.sync.aligned.m8n8.x2.shared.b16 {%0,%1}, [%2];" \
        : "=r"(r0), "=r"(r1) : "r"(addr))

__device__ __forceinline__ void mma_f32acc(float* c, const uint32_t* a, uint32_t b0, uint32_t b1) {
    asm volatile(
        "mma.sync.aligned.m16n8k16.row.col.f32.f16.f16.f32 "
        "{%0,%1,%2,%3}, {%4,%5,%6,%7}, {%8,%9}, {%0,%1,%2,%3};\n"
        : "+f"(c[0]), "+f"(c[1]), "+f"(c[2]), "+f"(c[3])
        : "r"(a[0]), "r"(a[1]), "r"(a[2]), "r"(a[3]), "r"(b0), "r"(b1));
}

// ------ prep: degree count + x->fp16 + W->B^T fp16 (fused, disjoint blocks) ------
__global__ void prep_kernel(const int* __restrict__ ei, const float* __restrict__ x,
                            const float* __restrict__ W1l, const float* __restrict__ W1r,
                            const float* __restrict__ W2l, const float* __restrict__ W2r,
                            int E, int nb_count, int nb_conv) {
    int b = blockIdx.x;
    if (b < nb_count) {
        int e = b * 256 + threadIdx.x;
        if (e < E) atomicAdd(&g_deg[ei[E + e]], 1);
    } else if (b < nb_count + nb_conv) {
        int idx = (b - nb_count) * 256 + threadIdx.x;   // 0 .. N_NODES*128-1
        if (idx < N_NODES * 128) {
            float2 v = *(const float2*)&x[(size_t)idx * 2];
            g_feat[idx] = pack_f2h2(v.x, v.y);
        }
    } else {
        int idx = (b - nb_count - nb_conv) * 256 + threadIdx.x;  // 0..131071
        int layer = idx >> 16;
        int n  = (idx >> 8) & 255;
        int k2 = idx & 255;
        int k  = k2 * 2;
        const float* Wl = layer ? W2l : W1l;
        const float* Wr = layer ? W2r : W1r;
        float v0, v1;
        if (k < 256) { v0 = Wl[k * 256 + n]; v1 = Wl[(k + 1) * 256 + n]; }
        else         { v0 = Wr[(k - 256) * 256 + n]; v1 = Wr[(k - 255) * 256 + n]; }
        g_Bt[idx] = pack_f2h2(v0, v1);
    }
}

// single-block full scan: rowptr/cursor from deg; re-zeros deg for the next replay
#define SCAN_PER_T 49
__global__ void scanall_kernel(int E) {
    __shared__ int ssum[1024];
    int t = threadIdx.x;
    int base = t * SCAN_PER_T;
    int s = 0;
#pragma unroll 7
    for (int i = 0; i < SCAN_PER_T; i++) {
        int idx = base + i;
        int v = (idx < N_NODES) ? g_deg[idx] : 0;
        if (idx < N_NODES) g_rowptr[idx] = s;
        s += v;
    }
    ssum[t] = s;
    __syncthreads();
    for (int off = 1; off < 1024; off <<= 1) {
        int v = (t >= off) ? ssum[t - off] : 0;
        __syncthreads();
        ssum[t] += v;
        __syncthreads();
    }
    int tbase = ssum[t] - s;
#pragma unroll 7
    for (int i = 0; i < SCAN_PER_T; i++) {
        int idx = base + i;
        if (idx < N_NODES) {
            int r = g_rowptr[idx] + tbase;
            g_rowptr[idx] = r;
            g_cursor[idx] = r;
            g_deg[idx]    = 0;
        }
    }
    if (t == 0) g_rowptr[N_NODES] = E;
}

__global__ void scatter_kernel(const int* __restrict__ ei, int E) {
    int e = blockIdx.x * blockDim.x + threadIdx.x;
    if (e < E) {
        int src = ei[e];
        int dst = ei[E + e];
        int pos = atomicAdd(&g_cursor[dst], 1);
        g_eidx[pos] = src;
    }
}

// ---------------- mean aggregation: warp per row, uint4 gathers ----------------
__global__ void aggregate_kernel() {
    int w    = threadIdx.x >> 5;
    int lane = threadIdx.x & 31;
    int row  = blockIdx.x * 4 + w;
    const uint4* __restrict__ feat4 = (const uint4*)g_feat;   // 32 uint4 per row

    int start = g_rowptr[row];
    int end   = g_rowptr[row + 1];

    float acc[8];
#pragma unroll
    for (int i = 0; i < 8; i++) acc[i] = 0.f;

    int e = start;
    for (; e + 2 <= end; e += 2) {
        int s0 = g_eidx[e];
        int s1 = g_eidx[e + 1];
        uint4 u0 = feat4[s0 * 32 + lane];
        uint4 u1 = feat4[s1 * 32 + lane];
        acc_u4(acc, u0);
        acc_u4(acc, u1);
    }
    if (e < end) {
        uint4 u = feat4[g_eidx[e] * 32 + lane];
        acc_u4(acc, u);
    }

    int deg = end - start;
    float scale = (deg > 0) ? 1.f / (float)deg : 0.f;
    uint4 o;
    o.x = pack_f2h2(acc[0] * scale, acc[1] * scale);
    o.y = pack_f2h2(acc[2] * scale, acc[3] * scale);
    o.z = pack_f2h2(acc[4] * scale, acc[5] * scale);
    o.w = pack_f2h2(acc[6] * scale, acc[7] * scale);
    uint4* A4 = (uint4*)g_Ahi;                 // 64 uint4 per row
    A4[row * 64 + lane]      = o;              // mean half
    A4[row * 64 + 32 + lane] = feat4[row * 32 + lane];   // self half
}

// ---------------- fp16 mma.sync GEMM: BM=256, BN=128, 512 threads ----------------
// out[M x 256] = A(fp16, [M x 512]) @ B^T(fp16) + bias (opt relu)
#define ROWB 80
#define A_TILE_BYTES (256 * ROWB)      // 20480
#define B_TILE_BYTES (128 * ROWB)      // 10240
#define STAGE_BYTES (A_TILE_BYTES + B_TILE_BYTES)   // 30720
#define SM_DYN (2 * STAGE_BYTES)                     // 61440

template <bool RELU, bool OUT_FP16>
__global__ __launch_bounds__(512, 1) void gemm_f16_kernel(
    int layer, const float* __restrict__ bias, float* __restrict__ out_param)
{
    extern __shared__ char dsm[];
    __shared__ float bias_s[128];

    const uint32_t* __restrict__ Bt = g_Bt + (size_t)layer * 65536;

    int tid  = threadIdx.x;
    int wid  = tid >> 5;          // 0..15
    int lid  = tid & 31;
    int g    = lid >> 2;
    int tg   = lid & 3;
    int row0 = blockIdx.x * 256;
    int n0   = blockIdx.y * 128;

    int warp_m = (wid & 3) * 64;     // 4 warps in M (64 rows each)
    int warp_n = (wid >> 2) * 32;    // 4 warps in N (32 cols each)

    if (tid < 128) bias_s[tid] = bias[n0 + tid];

    uint32_t s_base = smem_to_u32(dsm);

    uint32_t a_lane_off = (uint32_t)(((lid & 7) + ((lid >> 3) & 1) * 8) * ROWB + (lid >> 4) * 16);
    uint32_t b_lane_off = (uint32_t)((lid & 7) * ROWB + (((lid & 15) >> 3)) * 16);

    float acc[4][4][4];
#pragma unroll
    for (int mi = 0; mi < 4; mi++)
#pragma unroll
        for (int ni = 0; ni < 4; ni++)
#pragma unroll
            for (int r = 0; r < 4; r++) acc[mi][ni][r] = 0.f;

    // cp.async roles:
    //   A: 256 rows, 2 threads/row, 32B each  -> 2 cp of 16B
    //   B: 128 rows, 4 threads/row, 16B each  -> 1 cp
    int a_row = tid >> 1;            // 0..255
    int a_seg = (tid & 1) * 32;
    int b_row = tid >> 2;            // 0..127
    int b_seg = (tid & 3) * 16;
    int gr    = row0 + a_row;
    int a_sz  = (gr < N_NODES) ? 16 : 0;
    int gra   = (gr < N_NODES) ? gr : (N_NODES - 1);
    const char* aS = (const char*)(g_Ahi + (size_t)gra * 256) + a_seg;
    const char* bS = (const char*)(Bt + (size_t)(n0 + b_row) * 256) + b_seg;
    uint32_t a_dst = a_row * ROWB + a_seg;
    uint32_t b_dst = A_TILE_BYTES + b_row * ROWB + b_seg;

    auto tile_load = [&](int kt, int stage) {
        uint32_t st = s_base + stage * STAGE_BYTES;
        const char* srcA = aS + kt * 64;
        const char* srcB = bS + kt * 64;
        CP_ASYNC16(st + a_dst,      srcA,      a_sz);
        CP_ASYNC16(st + a_dst + 16, srcA + 16, a_sz);
        CP_ASYNC16(st + b_dst,      srcB,      16);
    };

    tile_load(0, 0);
    CP_COMMIT();

    for (int kt = 0; kt < 16; kt++) {
        int st = kt & 1;
        if (kt + 1 < 16) { tile_load(kt + 1, st ^ 1); CP_COMMIT(); CP_WAIT1(); }
        else             { CP_WAIT0(); }
        __syncthreads();

        uint32_t sa = s_base + st * STAGE_BYTES;
        uint32_t sb = sa + A_TILE_BYTES;

#pragma unroll
        for (int ks = 0; ks < 2; ks++) {
            uint32_t koff = ks * 32;
            uint32_t bh[4][2];
#pragma unroll
            for (int ni = 0; ni < 4; ni++) {
                uint32_t nbase = (uint32_t)((warp_n + ni * 8) * ROWB) + koff;
                LDSM_X2(bh[ni][0], bh[ni][1], sb + nbase + b_lane_off);
            }
#pragma unroll
            for (int mi = 0; mi < 4; mi++) {
                uint32_t mbase = (uint32_t)((warp_m + mi * 16) * ROWB) + koff;
                uint32_t ah[4];
                LDSM_X4(ah[0], ah[1], ah[2], ah[3], sa + mbase + a_lane_off);
#pragma unroll
                for (int ni = 0; ni < 4; ni++) mma_f32acc(acc[mi][ni], ah, bh[ni][0], bh[ni][1]);
            }
        }
        __syncthreads();
    }

    // epilogue
#pragma unroll
    for (int mi = 0; mi < 4; mi++) {
#pragma unroll
        for (int ni = 0; ni < 4; ni++) {
            int lc = warp_n + ni * 8 + tg * 2;
            float bx = bias_s[lc], by = bias_s[lc + 1];
            int gc  = n0 + lc;
            int gr0 = row0 + warp_m + mi * 16 + g;
            int gr1 = gr0 + 8;
            float2 v0, v1;
            v0.x = acc[mi][ni][0] + bx; v0.y = acc[mi][ni][1] + by;
            v1.x = acc[mi][ni][2] + bx; v1.y = acc[mi][ni][3] + by;
            if (RELU) {
                v0.x = fmaxf(v0.x, 0.f); v0.y = fmaxf(v0.y, 0.f);
                v1.x = fmaxf(v1.x, 0.f); v1.y = fmaxf(v1.y, 0.f);
            }
            if (OUT_FP16) {
                if (gr0 < N_NODES) g_feat[(size_t)gr0 * 128 + (gc >> 1)] = pack_f2h2(v0.x, v0.y);
                if (gr1 < N_NODES) g_feat[(size_t)gr1 * 128 + (gc >> 1)] = pack_f2h2(v1.x, v1.y);
            } else {
                if (gr0 < N_NODES) *(float2*)&out_param[(size_t)gr0 * D + gc] = v0;
                if (gr1 < N_NODES) *(float2*)&out_param[(size_t)gr1 * D + gc] = v1;
            }
        }
    }
}

// ---------------- launch ----------------
extern "C" void kernel_launch(void* const* d_in, const int* in_sizes, int n_in,
                              void* d_out, int out_size)
{
    const float* x   = (const float*)d_in[0];
    const int*   ei  = (const int*)d_in[1];     // JAX randint -> int32 (x64 disabled)
    const float* W1l = (const float*)d_in[2];
    const float* b1  = (const float*)d_in[3];
    const float* W1r = (const float*)d_in[4];
    const float* W2l = (const float*)d_in[5];
    const float* b2  = (const float*)d_in[6];
    const float* W2r = (const float*)d_in[7];
    float*       out = (float*)d_out;

    int E = in_sizes[1] / 2;
    if (E > E_MAX) E = E_MAX;

    cudaFuncSetAttribute(gemm_f16_kernel<true, true>,
                         cudaFuncAttributeMaxDynamicSharedMemorySize, SM_DYN);
    cudaFuncSetAttribute(gemm_f16_kernel<false, false>,
                         cudaFuncAttributeMaxDynamicSharedMemorySize, SM_DYN);

    int nb_count = (E + 255) / 256;
    int nb_conv  = (N_NODES * 128 + 255) / 256;
    int nb_w     = 512;

    // 0: degree count + x->fp16 + W convert (fused)
    prep_kernel<<<nb_count + nb_conv + nb_w, 256>>>(ei, x, W1l, W1r, W2l, W2r,
                                                    E, nb_count, nb_conv);
    // 1: scan (re-zeros deg for next replay)
    scanall_kernel<<<1, 1024>>>(E);
    // 2: CSR scatter
    scatter_kernel<<<nb_count, 256>>>(ei, E);
    // 3: layer-1 aggregation (profiled slot)
    aggregate_kernel<<<N_NODES / 4, 128>>>();

    dim3 ggrid((N_NODES + 255) / 256, 2);   // 196 x 2
    // 4: layer-1 GEMM -> g_feat (fp16 relu h)
    gemm_f16_kernel<true, true><<<ggrid, 512, SM_DYN>>>(0, b1, nullptr);
    // 5: layer-2 aggregation
    aggregate_kernel<<<N_NODES / 4, 128>>>();
    // 6: layer-2 GEMM -> out (f32)
    gemm_f16_kernel<false, false><<<ggrid, 512, SM_DYN>>>(1, b2, out);
}

// round 14
// speedup vs baseline: 1.5972x; 1.1171x over previous
#include <cuda_runtime.h>
#include <cuda_fp16.h>
#include <cstdint>

#define N_NODES 50000
#define N_PAD   50176           // 196 * 256
#define D 256
#define E_MAX 800000

// ---------------- scratch (static device globals; no allocation) ----------------
__device__ int   g_deg[N_NODES];
__device__ int   g_rowptr[N_NODES + 1];
__device__ int   g_cursor[N_NODES];
__device__ int   g_eidx[E_MAX];
// current-layer features fp16 pairs: [row][t(128)] u32
__device__ __align__(16) uint32_t g_feat[(size_t)N_NODES * 128];
// A in k-tiled swizzled layout: [kt(16)][row(N_PAD)][16 u32 = 64B]
//   kt 0..7 = mean half (k 0..255), kt 8..15 = self half
//   16B segment s of row r stored at physical seg (s + (r>>1)) & 3
__device__ __align__(16) uint32_t g_A[(size_t)16 * N_PAD * 16];
// B^T k-tiled swizzled: [layer][kt(16)][n(256)][16 u32]
__device__ __align__(16) uint32_t g_Bt[2 * 16 * 256 * 16];

// ---------------- small helpers ----------------
__device__ __forceinline__ uint32_t smem_to_u32(const void* p) {
    uint32_t a;
    asm("{ .reg .u64 t; cvta.to.shared.u64 t, %1; cvt.u32.u64 %0, t; }" : "=r"(a) : "l"(p));
    return a;
}

__device__ __forceinline__ uint32_t pack_h2(__half a, __half b) {
    __half2 h = __halves2half2(a, b);
    return *reinterpret_cast<uint32_t*>(&h);
}

__device__ __forceinline__ uint32_t pack_f2h2(float a, float b) {
    return pack_h2(__float2half_rn(a), __float2half_rn(b));
}

__device__ __forceinline__ void acc_u4(float* a, uint4 u) {
    float2 f0 = __half22float2(*reinterpret_cast<__half2*>(&u.x));
    float2 f1 = __half22float2(*reinterpret_cast<__half2*>(&u.y));
    float2 f2 = __half22float2(*reinterpret_cast<__half2*>(&u.z));
    float2 f3 = __half22float2(*reinterpret_cast<__half2*>(&u.w));
    a[0] += f0.x; a[1] += f0.y; a[2] += f1.x; a[3] += f1.y;
    a[4] += f2.x; a[5] += f2.y; a[6] += f3.x; a[7] += f3.y;
}

#define LDSM_X4(r0, r1, r2, r3, addr) \
    asm volatile("ldmatrix.sync.aligned.m8n8.x4.shared.b16 {%0,%1,%2,%3}, [%4];" \
        : "=r"(r0), "=r"(r1), "=r"(r2), "=r"(r3) : "r"(addr))
#define LDSM_X2(r0, r1, addr) \
    asm volatile("ldmatrix.sync.aligned.m8n8.x2.shared.b16 {%0,%1}, [%2];" \
        : "=r"(r0), "=r"(r1) : "r"(addr))

__device__ __forceinline__ void mma_f32acc(float* c, const uint32_t* a, uint32_t b0, uint32_t b1) {
    asm volatile(
        "mma.sync.aligned.m16n8k16.row.col.f32.f16.f16.f32 "
        "{%0,%1,%2,%3}, {%4,%5,%6,%7}, {%8,%9}, {%0,%1,%2,%3};\n"
        : "+f"(c[0]), "+f"(c[1]), "+f"(c[2]), "+f"(c[3])
        : "r"(a[0]), "r"(a[1]), "r"(a[2]), "r"(a[3]), "r"(b0), "r"(b1));
}

// bulk async copy: gmem -> smem, completion via mbarrier complete_tx
#define BULK_CP(dst, src, size, mbar) \
    asm volatile("cp.async.bulk.shared::cluster.global.mbarrier::complete_tx::bytes [%0], [%1], %2, [%3];" \
        :: "r"(dst), "l"(src), "r"(size), "r"(mbar) : "memory")

#define MBARRIER_INIT(mbar, count) \
    asm volatile("mbarrier.init.shared.b64 [%0], %1;" \
        :: "r"((uint32_t)(mbar)), "r"((uint32_t)(count)) : "memory")
#define MBARRIER_EXPECT_TX(mbar, tx) \
    asm volatile("mbarrier.arrive.expect_tx.shared.b64 _, [%0], %1;" \
        :: "r"((uint32_t)(mbar)), "r"((uint32_t)(tx)) : "memory")

#define MBARRIER_WAIT_PARITY(mbar, parity) do { \
    uint32_t _mbar = (uint32_t)(mbar); \
    uint32_t _parity = (uint32_t)(parity); \
    uint32_t _done; \
    asm volatile("{\n\t.reg .pred p;\n\t" \
        "mbarrier.try_wait.parity.acquire.cta.shared::cta.b64 p, [%1], %2;\n\t" \
        "selp.b32 %0, 1, 0, p;\n\t}" : "=r"(_done) : "r"(_mbar), "r"(_parity) : "memory"); \
    if (!_done) { \
        asm volatile("{\n\t.reg .pred P1;\n\t" \
            "WAIT_LOOP_%=:\n\t" \
            "mbarrier.try_wait.parity.acquire.cta.shared::cta.b64 P1, [%0], %1, 0x989680;\n\t" \
            "@P1 bra.uni WAIT_DONE_%=;\n\t" \
            "bra.uni WAIT_LOOP_%=;\n\t" \
            "WAIT_DONE_%=:\n\t}" :: "r"(_mbar), "r"(_parity) : "memory"); \
    } \
} while(0)

// ------ prep: degree count + x->fp16 feature convert (disjoint blocks) ------
__global__ void prep_kernel(const int* __restrict__ ei, const float* __restrict__ x,
                            int E, int nb_count) {
    int b = blockIdx.x;
    if (b < nb_count) {
        int e = b * 256 + threadIdx.x;
        if (e < E) atomicAdd(&g_deg[ei[E + e]], 1);
    } else {
        int idx = (b - nb_count) * 256 + threadIdx.x;   // 0 .. N_NODES*128-1
        if (idx < N_NODES * 128) {
            float2 v = *(const float2*)&x[(size_t)idx * 2];
            g_feat[idx] = pack_f2h2(v.x, v.y);
        }
    }
}

// ------ W -> B^T k-tiled swizzled fp16 ------
__global__ void convert_w_kernel(const float* __restrict__ W1l, const float* __restrict__ W1r,
                                 const float* __restrict__ W2l, const float* __restrict__ W2r) {
    int idx = blockIdx.x * 256 + threadIdx.x;        // 0..131071
    int layer = idx >> 16;
    int n  = (idx >> 8) & 255;
    int k2 = idx & 255;
    int k  = k2 * 2;
    const float* Wl = layer ? W2l : W1l;
    const float* Wr = layer ? W2r : W1r;
    float v0, v1;
    if (k < 256) { v0 = Wl[k * 256 + n]; v1 = Wl[(k + 1) * 256 + n]; }
    else         { v0 = Wr[(k - 256) * 256 + n]; v1 = Wr[(k - 255) * 256 + n]; }
    int kt   = k2 >> 4;
    int seg  = (k2 >> 2) & 3;
    int phys = (seg + (n >> 1)) & 3;
    int inner = k2 & 3;
    g_Bt[(((size_t)layer * 16 + kt) * 256 + n) * 16 + phys * 4 + inner] = pack_f2h2(v0, v1);
}

// single-block full scan
#define SCAN_PER_T 49
__global__ void scanall_kernel(int E) {
    __shared__ int ssum[1024];
    int t = threadIdx.x;
    int base = t * SCAN_PER_T;
    int s = 0;
#pragma unroll 7
    for (int i = 0; i < SCAN_PER_T; i++) {
        int idx = base + i;
        int v = (idx < N_NODES) ? g_deg[idx] : 0;
        if (idx < N_NODES) g_rowptr[idx] = s;
        s += v;
    }
    ssum[t] = s;
    __syncthreads();
    for (int off = 1; off < 1024; off <<= 1) {
        int v = (t >= off) ? ssum[t - off] : 0;
        __syncthreads();
        ssum[t] += v;
        __syncthreads();
    }
    int tbase = ssum[t] - s;
#pragma unroll 7
    for (int i = 0; i < SCAN_PER_T; i++) {
        int idx = base + i;
        if (idx < N_NODES) {
            int r = g_rowptr[idx] + tbase;
            g_rowptr[idx] = r;
            g_cursor[idx] = r;
            g_deg[idx]    = 0;
        }
    }
    if (t == 0) g_rowptr[N_NODES] = E;
}

__global__ void scatter_kernel(const int* __restrict__ ei, int E) {
    int e = blockIdx.x * blockDim.x + threadIdx.x;
    if (e < E) {
        int src = ei[e];
        int dst = ei[E + e];
        int pos = atomicAdd(&g_cursor[dst], 1);
        g_eidx[pos] = src;
    }
}

// ---------------- mean aggregation: warp per row -> k-tiled swizzled A ----------------
__global__ void aggregate_kernel() {
    int w    = threadIdx.x >> 5;
    int lane = threadIdx.x & 31;
    int row  = blockIdx.x * 4 + w;
    const uint4* __restrict__ feat4 = (const uint4*)g_feat;   // 32 uint4 per row

    int start = g_rowptr[row];
    int end   = g_rowptr[row + 1];

    float acc[8];
#pragma unroll
    for (int i = 0; i < 8; i++) acc[i] = 0.f;

    int e = start;
    for (; e + 2 <= end; e += 2) {
        int s0 = g_eidx[e];
        int s1 = g_eidx[e + 1];
        uint4 u0 = feat4[s0 * 32 + lane];
        uint4 u1 = feat4[s1 * 32 + lane];
        acc_u4(acc, u0);
        acc_u4(acc, u1);
    }
    if (e < end) {
        uint4 u = feat4[g_eidx[e] * 32 + lane];
        acc_u4(acc, u);
    }

    int deg = end - start;
    float scale = (deg > 0) ? 1.f / (float)deg : 0.f;
    uint4 o;
    o.x = pack_f2h2(acc[0] * scale, acc[1] * scale);
    o.y = pack_f2h2(acc[2] * scale, acc[3] * scale);
    o.z = pack_f2h2(acc[4] * scale, acc[5] * scale);
    o.w = pack_f2h2(acc[6] * scale, acc[7] * scale);
    // k-tiled swizzled stores: lane covers k2 4l..4l+3 -> kt=l>>2, seg=l&3
    int kt   = lane >> 2;
    int phys = ((lane & 3) + (row >> 1)) & 3;
    uint4* A4 = (uint4*)g_A;
    A4[((size_t)kt * N_PAD + row) * 4 + phys]       = o;                       // mean: kt 0..7
    A4[((size_t)(kt + 8) * N_PAD + row) * 4 + phys] = feat4[row * 32 + lane];  // self: kt 8..15
}

// ---------------- fp16 mma.sync GEMM with cp.async.bulk tile loads ----------------
// BM=256, BN=128, 512 threads; A/B tiles contiguous (pre-swizzled) -> 2 bulk copies/stage
#define A_TILE_B 16384
#define B_TILE_B 8192
#define STAGE_B  (A_TILE_B + B_TILE_B)   // 24576
#define SM_DYN   (2 * STAGE_B)           // 49152

template <bool RELU, bool OUT_FP16>
__global__ __launch_bounds__(512, 1) void gemm_f16_kernel(
    int layer, const float* __restrict__ bias, float* __restrict__ out_param)
{
    extern __shared__ char dsm[];
    __shared__ float bias_s[128];
    __shared__ __align__(8) unsigned long long mbar_s[2];

    int tid  = threadIdx.x;
    int wid  = tid >> 5;          // 0..15
    int lid  = tid & 31;
    int g    = lid >> 2;
    int tg   = lid & 3;
    int row0 = blockIdx.x * 256;
    int n0   = blockIdx.y * 128;

    int warp_m = (wid & 3) * 64;     // 4 warps in M
    int warp_n = (wid >> 2) * 32;    // 4 warps in N

    if (tid < 128) bias_s[tid] = bias[n0 + tid];

    uint32_t s_base    = smem_to_u32(dsm);
    uint32_t mbar_base = smem_to_u32(mbar_s);

    if (tid == 0) {
        MBARRIER_INIT(mbar_base,     1);
        MBARRIER_INIT(mbar_base + 8, 1);
    }
    __syncthreads();

    // per-lane ldmatrix offsets (swizzle (seg + (row>>1))&3 baked into layout)
    int lrA = (lid & 7) + ((lid >> 3) & 1) * 8;
    uint32_t a_off0 = (uint32_t)(lrA * 64 + ((((lid >> 4))     + (lrA >> 1)) & 3) * 16);
    uint32_t a_off1 = (uint32_t)(lrA * 64 + ((((lid >> 4)) + 2 + (lrA >> 1)) & 3) * 16);
    int lrB = lid & 7;
    uint32_t b_off0 = (uint32_t)(lrB * 64 + (((((lid & 15) >> 3))     + (lrB >> 1)) & 3) * 16);
    uint32_t b_off1 = (uint32_t)(lrB * 64 + (((((lid & 15) >> 3)) + 2 + (lrB >> 1)) & 3) * 16);

    float acc[4][4][4];
#pragma unroll
    for (int mi = 0; mi < 4; mi++)
#pragma unroll
        for (int ni = 0; ni < 4; ni++)
#pragma unroll
            for (int r = 0; r < 4; r++) acc[mi][ni][r] = 0.f;

    const char* aBase = (const char*)g_A + (size_t)row0 * 64;
    const char* bBase = (const char*)g_Bt + ((size_t)layer * 16 * 256 + n0) * 64;

    auto issue = [&](int kt, int st) {
        uint32_t mb = mbar_base + st * 8;
        MBARRIER_EXPECT_TX(mb, STAGE_B);
        uint32_t d = s_base + st * STAGE_B;
        BULK_CP(d,            aBase + (size_t)kt * N_PAD * 64, A_TILE_B, mb);
        BULK_CP(d + A_TILE_B, bBase + (size_t)kt * 256 * 64,   B_TILE_B, mb);
    };

    if (tid == 0) issue(0, 0);
    int ph0 = 0, ph1 = 0;

    for (int kt = 0; kt < 16; kt++) {
        int st = kt & 1;
        if (tid == 0 && kt + 1 < 16) issue(kt + 1, st ^ 1);

        uint32_t mb = mbar_base + st * 8;
        if (st) { MBARRIER_WAIT_PARITY(mb, ph1); ph1 ^= 1; }
        else    { MBARRIER_WAIT_PARITY(mb, ph0); ph0 ^= 1; }

        uint32_t sa = s_base + st * STAGE_B;
        uint32_t sb = sa + A_TILE_B;

#pragma unroll
        for (int ks = 0; ks < 2; ks++) {
            uint32_t ao = ks ? a_off1 : a_off0;
            uint32_t bo = ks ? b_off1 : b_off0;
            uint32_t bh[4][2];
#pragma unroll
            for (int ni = 0; ni < 4; ni++)
                LDSM_X2(bh[ni][0], bh[ni][1], sb + (uint32_t)((warp_n + ni * 8) * 64) + bo);
#pragma unroll
            for (int mi = 0; mi < 4; mi++) {
                uint32_t ah[4];
                LDSM_X4(ah[0], ah[1], ah[2], ah[3], sa + (uint32_t)((warp_m + mi * 16) * 64) + ao);
#pragma unroll
                for (int ni = 0; ni < 4; ni++) mma_f32acc(acc[mi][ni], ah, bh[ni][0], bh[ni][1]);
            }
        }
        __syncthreads();   // all reads of stage st done before it is re-filled
    }

    // epilogue
#pragma unroll
    for (int mi = 0; mi < 4; mi++) {
#pragma unroll
        for (int ni = 0; ni < 4; ni++) {
            int lc = warp_n + ni * 8 + tg * 2;
            float bx = bias_s[lc], by = bias_s[lc + 1];
            int gc  = n0 + lc;
            int gr0 = row0 + warp_m + mi * 16 + g;
            int gr1 = gr0 + 8;
            float2 v0, v1;
            v0.x = acc[mi][ni][0] + bx; v0.y = acc[mi][ni][1] + by;
            v1.x = acc[mi][ni][2] + bx; v1.y = acc[mi][ni][3] + by;
            if (RELU) {
                v0.x = fmaxf(v0.x, 0.f); v0.y = fmaxf(v0.y, 0.f);
                v1.x = fmaxf(v1.x, 0.f); v1.y = fmaxf(v1.y, 0.f);
            }
            if (OUT_FP16) {
                if (gr0 < N_NODES) g_feat[(size_t)gr0 * 128 + (gc >> 1)] = pack_f2h2(v0.x, v0.y);
                if (gr1 < N_NODES) g_feat[(size_t)gr1 * 128 + (gc >> 1)] = pack_f2h2(v1.x, v1.y);
            } else {
                if (gr0 < N_NODES) *(float2*)&out_param[(size_t)gr0 * D + gc] = v0;
                if (gr1 < N_NODES) *(float2*)&out_param[(size_t)gr1 * D + gc] = v1;
            }
        }
    }
}

// ---------------- launch ----------------
extern "C" void kernel_launch(void* const* d_in, const int* in_sizes, int n_in,
                              void* d_out, int out_size)
{
    const float* x   = (const float*)d_in[0];
    const int*   ei  = (const int*)d_in[1];     // JAX randint -> int32 (x64 disabled)
    const float* W1l = (const float*)d_in[2];
    const float* b1  = (const float*)d_in[3];
    const float* W1r = (const float*)d_in[4];
    const float* W2l = (const float*)d_in[5];
    const float* b2  = (const float*)d_in[6];
    const float* W2r = (const float*)d_in[7];
    float*       out = (float*)d_out;

    int E = in_sizes[1] / 2;
    if (E > E_MAX) E = E_MAX;

    cudaFuncSetAttribute(gemm_f16_kernel<true, true>,
                         cudaFuncAttributeMaxDynamicSharedMemorySize, SM_DYN);
    cudaFuncSetAttribute(gemm_f16_kernel<false, false>,
                         cudaFuncAttributeMaxDynamicSharedMemorySize, SM_DYN);

    int nb_count = (E + 255) / 256;
    int nb_conv  = (N_NODES * 128 + 255) / 256;

    // 0: degree count + x->fp16
    prep_kernel<<<nb_count + nb_conv, 256>>>(ei, x, E, nb_count);
    // 1: scan (re-zeros deg for next replay)
    scanall_kernel<<<1, 1024>>>(E);
    // 2: CSR scatter
    scatter_kernel<<<nb_count, 256>>>(ei, E);
    // 3: weight conversion
    convert_w_kernel<<<512, 256>>>(W1l, W1r, W2l, W2r);
    // 4: layer-1 aggregation
    aggregate_kernel<<<N_NODES / 4, 128>>>();

    dim3 ggrid((N_PAD + 255) / 256, 2);   // 196 x 2
    // 5: layer-1 GEMM -> g_feat (profiled slot)
    gemm_f16_kernel<true, true><<<ggrid, 512, SM_DYN>>>(0, b1, nullptr);
    // 6: layer-2 aggregation
    aggregate_kernel<<<N_NODES / 4, 128>>>();
    // 7: layer-2 GEMM -> out (f32)
    gemm_f16_kernel<false, false><<<ggrid, 512, SM_DYN>>>(1, b2, out);
}

// round 15
// speedup vs baseline: 1.6210x; 1.0149x over previous
#include <cuda_runtime.h>
#include <cuda_fp16.h>
#include <cstdint>

#define N_NODES 50000
#define N_PAD   50176           // 196 * 256
#define D 256
#define E_MAX 800000

// ---------------- scratch (static device globals; no allocation) ----------------
__device__ int   g_deg[N_NODES];
__device__ int   g_rowptr[N_NODES + 1];
__device__ int   g_cursor[N_NODES];
__device__ int   g_eidx[E_MAX];
// current-layer features fp16 pairs: [row][t(128)] u32
__device__ __align__(16) uint32_t g_feat[(size_t)N_NODES * 128];
// A k-tiled swizzled: [kt(16)][row(N_PAD)][16 u32]; seg s of row r at phys (s+(r>>1))&3
__device__ __align__(16) uint32_t g_A[(size_t)16 * N_PAD * 16];
// B^T k-tiled swizzled: [layer][kt(16)][n(256)][16 u32]
__device__ __align__(16) uint32_t g_Bt[2 * 16 * 256 * 16];

// ---------------- small helpers ----------------
__device__ __forceinline__ uint32_t smem_to_u32(const void* p) {
    uint32_t a;
    asm("{ .reg .u64 t; cvta.to.shared.u64 t, %1; cvt.u32.u64 %0, t; }" : "=r"(a) : "l"(p));
    return a;
}

__device__ __forceinline__ uint32_t pack_h2(__half a, __half b) {
    __half2 h = __halves2half2(a, b);
    return *reinterpret_cast<uint32_t*>(&h);
}

__device__ __forceinline__ uint32_t pack_f2h2(float a, float b) {
    return pack_h2(__float2half_rn(a), __float2half_rn(b));
}

__device__ __forceinline__ uint32_t hadd2(uint32_t a, uint32_t b) {
    uint32_t r;
    asm("add.rn.f16x2 %0, %1, %2;" : "=r"(r) : "r"(a), "r"(b));
    return r;
}

__device__ __forceinline__ void acc_u4(float* a, uint4 u) {
    float2 f0 = __half22float2(*reinterpret_cast<__half2*>(&u.x));
    float2 f1 = __half22float2(*reinterpret_cast<__half2*>(&u.y));
    float2 f2 = __half22float2(*reinterpret_cast<__half2*>(&u.z));
    float2 f3 = __half22float2(*reinterpret_cast<__half2*>(&u.w));
    a[0] += f0.x; a[1] += f0.y; a[2] += f1.x; a[3] += f1.y;
    a[4] += f2.x; a[5] += f2.y; a[6] += f3.x; a[7] += f3.y;
}

#define LDSM_X4(r0, r1, r2, r3, addr) \
    asm volatile("ldmatrix.sync.aligned.m8n8.x4.shared.b16 {%0,%1,%2,%3}, [%4];" \
        : "=r"(r0), "=r"(r1), "=r"(r2), "=r"(r3) : "r"(addr))
#define LDSM_X2(r0, r1, addr) \
    asm volatile("ldmatrix.sync.aligned.m8n8.x2.shared.b16 {%0,%1}, [%2];" \
        : "=r"(r0), "=r"(r1) : "r"(addr))

__device__ __forceinline__ void mma_f32acc(float* c, const uint32_t* a, uint32_t b0, uint32_t b1) {
    asm volatile(
        "mma.sync.aligned.m16n8k16.row.col.f32.f16.f16.f32 "
        "{%0,%1,%2,%3}, {%4,%5,%6,%7}, {%8,%9}, {%0,%1,%2,%3};\n"
        : "+f"(c[0]), "+f"(c[1]), "+f"(c[2]), "+f"(c[3])
        : "r"(a[0]), "r"(a[1]), "r"(a[2]), "r"(a[3]), "r"(b0), "r"(b1));
}

#define BULK_CP(dst, src, size, mbar) \
    asm volatile("cp.async.bulk.shared::cluster.global.mbarrier::complete_tx::bytes [%0], [%1], %2, [%3];" \
        :: "r"(dst), "l"(src), "r"(size), "r"(mbar) : "memory")

#define MBARRIER_INIT(mbar, count) \
    asm volatile("mbarrier.init.shared.b64 [%0], %1;" \
        :: "r"((uint32_t)(mbar)), "r"((uint32_t)(count)) : "memory")
#define MBARRIER_EXPECT_TX(mbar, tx) \
    asm volatile("mbarrier.arrive.expect_tx.shared.b64 _, [%0], %1;" \
        :: "r"((uint32_t)(mbar)), "r"((uint32_t)(tx)) : "memory")

#define MBARRIER_WAIT_PARITY(mbar, parity) do { \
    uint32_t _mbar = (uint32_t)(mbar); \
    uint32_t _parity = (uint32_t)(parity); \
    uint32_t _done; \
    asm volatile("{\n\t.reg .pred p;\n\t" \
        "mbarrier.try_wait.parity.acquire.cta.shared::cta.b64 p, [%1], %2;\n\t" \
        "selp.b32 %0, 1, 0, p;\n\t}" : "=r"(_done) : "r"(_mbar), "r"(_parity) : "memory"); \
    if (!_done) { \
        asm volatile("{\n\t.reg .pred P1;\n\t" \
            "WAIT_LOOP_%=:\n\t" \
            "mbarrier.try_wait.parity.acquire.cta.shared::cta.b64 P1, [%0], %1, 0x989680;\n\t" \
            "@P1 bra.uni WAIT_DONE_%=;\n\t" \
            "bra.uni WAIT_LOOP_%=;\n\t" \
            "WAIT_DONE_%=:\n\t}" :: "r"(_mbar), "r"(_parity) : "memory"); \
    } \
} while(0)

// ------ prep: degree count + x->fp16 (disjoint blocks) ------
__global__ void prep_kernel(const int* __restrict__ ei, const float* __restrict__ x,
                            int E, int nb_count) {
    int b = blockIdx.x;
    if (b < nb_count) {
        int e = b * 256 + threadIdx.x;
        if (e < E) atomicAdd(&g_deg[ei[E + e]], 1);
    } else {
        int idx = (b - nb_count) * 256 + threadIdx.x;
        if (idx < N_NODES * 128) {
            float2 v = *(const float2*)&x[(size_t)idx * 2];
            g_feat[idx] = pack_f2h2(v.x, v.y);
        }
    }
}

// ------ W -> B^T k-tiled swizzled fp16 ------
__global__ void convert_w_kernel(const float* __restrict__ W1l, const float* __restrict__ W1r,
                                 const float* __restrict__ W2l, const float* __restrict__ W2r) {
    int idx = blockIdx.x * 256 + threadIdx.x;        // 0..131071
    int layer = idx >> 16;
    int n  = (idx >> 8) & 255;
    int k2 = idx & 255;
    int k  = k2 * 2;
    const float* Wl = layer ? W2l : W1l;
    const float* Wr = layer ? W2r : W1r;
    float v0, v1;
    if (k < 256) { v0 = Wl[k * 256 + n]; v1 = Wl[(k + 1) * 256 + n]; }
    else         { v0 = Wr[(k - 256) * 256 + n]; v1 = Wr[(k - 255) * 256 + n]; }
    int kt   = k2 >> 4;
    int seg  = (k2 >> 2) & 3;
    int phys = (seg + (n >> 1)) & 3;
    int inner = k2 & 3;
    g_Bt[(((size_t)layer * 16 + kt) * 256 + n) * 16 + phys * 4 + inner] = pack_f2h2(v0, v1);
}

// single-block full scan
#define SCAN_PER_T 49
__global__ void scanall_kernel(int E) {
    __shared__ int ssum[1024];
    int t = threadIdx.x;
    int base = t * SCAN_PER_T;
    int s = 0;
#pragma unroll 7
    for (int i = 0; i < SCAN_PER_T; i++) {
        int idx = base + i;
        int v = (idx < N_NODES) ? g_deg[idx] : 0;
        if (idx < N_NODES) g_rowptr[idx] = s;
        s += v;
    }
    ssum[t] = s;
    __syncthreads();
    for (int off = 1; off < 1024; off <<= 1) {
        int v = (t >= off) ? ssum[t - off] : 0;
        __syncthreads();
        ssum[t] += v;
        __syncthreads();
    }
    int tbase = ssum[t] - s;
#pragma unroll 7
    for (int i = 0; i < SCAN_PER_T; i++) {
        int idx = base + i;
        if (idx < N_NODES) {
            int r = g_rowptr[idx] + tbase;
            g_rowptr[idx] = r;
            g_cursor[idx] = r;
            g_deg[idx]    = 0;
        }
    }
    if (t == 0) g_rowptr[N_NODES] = E;
}

__global__ void scatter_kernel(const int* __restrict__ ei, int E) {
    int e = blockIdx.x * blockDim.x + threadIdx.x;
    if (e < E) {
        int src = ei[e];
        int dst = ei[E + e];
        int pos = atomicAdd(&g_cursor[dst], 1);
        g_eidx[pos] = src;
    }
}

// ---------------- mean aggregation: warp/row, pairwise fp16 pre-add ----------------
__global__ void aggregate_kernel() {
    int w    = threadIdx.x >> 5;
    int lane = threadIdx.x & 31;
    int row  = blockIdx.x * 4 + w;
    const uint4* __restrict__ feat4 = (const uint4*)g_feat;   // 32 uint4 per row

    int start = g_rowptr[row];
    int end   = g_rowptr[row + 1];

    float acc[8];
#pragma unroll
    for (int i = 0; i < 8; i++) acc[i] = 0.f;

    int e = start;
    for (; e + 4 <= end; e += 4) {
        int s0 = g_eidx[e],     s1 = g_eidx[e + 1];
        int s2 = g_eidx[e + 2], s3 = g_eidx[e + 3];
        uint4 u0 = feat4[s0 * 32 + lane];
        uint4 u1 = feat4[s1 * 32 + lane];
        uint4 u2 = feat4[s2 * 32 + lane];
        uint4 u3 = feat4[s3 * 32 + lane];
        uint4 p01, p23;
        p01.x = hadd2(u0.x, u1.x); p01.y = hadd2(u0.y, u1.y);
        p01.z = hadd2(u0.z, u1.z); p01.w = hadd2(u0.w, u1.w);
        p23.x = hadd2(u2.x, u3.x); p23.y = hadd2(u2.y, u3.y);
        p23.z = hadd2(u2.z, u3.z); p23.w = hadd2(u2.w, u3.w);
        acc_u4(acc, p01);
        acc_u4(acc, p23);
    }
    if (e + 2 <= end) {
        uint4 u0 = feat4[g_eidx[e] * 32 + lane];
        uint4 u1 = feat4[g_eidx[e + 1] * 32 + lane];
        uint4 p;
        p.x = hadd2(u0.x, u1.x); p.y = hadd2(u0.y, u1.y);
        p.z = hadd2(u0.z, u1.z); p.w = hadd2(u0.w, u1.w);
        acc_u4(acc, p);
        e += 2;
    }
    if (e < end) {
        uint4 u = feat4[g_eidx[e] * 32 + lane];
        acc_u4(acc, u);
    }

    int deg = end - start;
    float scale = (deg > 0) ? 1.f / (float)deg : 0.f;
    uint4 o;
    o.x = pack_f2h2(acc[0] * scale, acc[1] * scale);
    o.y = pack_f2h2(acc[2] * scale, acc[3] * scale);
    o.z = pack_f2h2(acc[4] * scale, acc[5] * scale);
    o.w = pack_f2h2(acc[6] * scale, acc[7] * scale);
    int kt   = lane >> 2;
    int phys = ((lane & 3) + (row >> 1)) & 3;
    uint4* A4 = (uint4*)g_A;
    A4[((size_t)kt * N_PAD + row) * 4 + phys]       = o;                       // mean half
    A4[((size_t)(kt + 8) * N_PAD + row) * 4 + phys] = feat4[row * 32 + lane];  // self half
}

// ---------------- fp16 mma.sync GEMM: 3-stage cp.async.bulk pipeline ----------------
#define A_TILE_B 16384
#define B_TILE_B 8192
#define STAGE_B  (A_TILE_B + B_TILE_B)   // 24576
#define N_STAGE  3
#define SM_DYN   (N_STAGE * STAGE_B)     // 73728

template <bool RELU, bool OUT_FP16>
__global__ __launch_bounds__(512, 1) void gemm_f16_kernel(
    int layer, const float* __restrict__ bias, float* __restrict__ out_param)
{
    extern __shared__ char dsm[];
    __shared__ float bias_s[128];
    __shared__ __align__(8) unsigned long long mbar_s[N_STAGE];

    int tid  = threadIdx.x;
    int wid  = tid >> 5;
    int lid  = tid & 31;
    int g    = lid >> 2;
    int tg   = lid & 3;
    int row0 = blockIdx.x * 256;
    int n0   = blockIdx.y * 128;

    int warp_m = (wid & 3) * 64;
    int warp_n = (wid >> 2) * 32;

    if (tid < 128) bias_s[tid] = bias[n0 + tid];

    uint32_t s_base    = smem_to_u32(dsm);
    uint32_t mbar_base = smem_to_u32(mbar_s);

    if (tid == 0) {
#pragma unroll
        for (int s = 0; s < N_STAGE; s++) MBARRIER_INIT(mbar_base + s * 8, 1);
    }
    __syncthreads();

    int lrA = (lid & 7) + ((lid >> 3) & 1) * 8;
    uint32_t a_off0 = (uint32_t)(lrA * 64 + ((((lid >> 4))     + (lrA >> 1)) & 3) * 16);
    uint32_t a_off1 = (uint32_t)(lrA * 64 + ((((lid >> 4)) + 2 + (lrA >> 1)) & 3) * 16);
    int lrB = lid & 7;
    uint32_t b_off0 = (uint32_t)(lrB * 64 + (((((lid & 15) >> 3))     + (lrB >> 1)) & 3) * 16);
    uint32_t b_off1 = (uint32_t)(lrB * 64 + (((((lid & 15) >> 3)) + 2 + (lrB >> 1)) & 3) * 16);

    float acc[4][4][4];
#pragma unroll
    for (int mi = 0; mi < 4; mi++)
#pragma unroll
        for (int ni = 0; ni < 4; ni++)
#pragma unroll
            for (int r = 0; r < 4; r++) acc[mi][ni][r] = 0.f;

    const char* aBase = (const char*)g_A + (size_t)row0 * 64;
    const char* bBase = (const char*)g_Bt + ((size_t)layer * 16 * 256 + n0) * 64;

    auto issue = [&](int kt, int st) {
        uint32_t mb = mbar_base + st * 8;
        MBARRIER_EXPECT_TX(mb, STAGE_B);
        uint32_t d = s_base + st * STAGE_B;
        BULK_CP(d,            aBase + (size_t)kt * N_PAD * 64, A_TILE_B, mb);
        BULK_CP(d + A_TILE_B, bBase + (size_t)kt * 256 * 64,   B_TILE_B, mb);
    };

    if (tid == 0) { issue(0, 0); issue(1, 1); }

    for (int kt = 0; kt < 16; kt++) {
        int st = kt % N_STAGE;
        // prefetch 2 tiles ahead: stage (kt+2)%3 was fully read at iteration kt-1
        // (guarded by the __syncthreads at the end of that iteration)
        if (tid == 0 && kt + 2 < 16) issue(kt + 2, (kt + 2) % N_STAGE);

        // parity of the (kt/3)-th use of this stage
        MBARRIER_WAIT_PARITY(mbar_base + st * 8, (kt / N_STAGE) & 1);

        uint32_t sa = s_base + st * STAGE_B;
        uint32_t sb = sa + A_TILE_B;

#pragma unroll
        for (int ks = 0; ks < 2; ks++) {
            uint32_t ao = ks ? a_off1 : a_off0;
            uint32_t bo = ks ? b_off1 : b_off0;
            uint32_t bh[4][2];
#pragma unroll
            for (int ni = 0; ni < 4; ni++)
                LDSM_X2(bh[ni][0], bh[ni][1], sb + (uint32_t)((warp_n + ni * 8) * 64) + bo);
#pragma unroll
            for (int mi = 0; mi < 4; mi++) {
                uint32_t ah[4];
                LDSM_X4(ah[0], ah[1], ah[2], ah[3], sa + (uint32_t)((warp_m + mi * 16) * 64) + ao);
#pragma unroll
                for (int ni = 0; ni < 4; ni++) mma_f32acc(acc[mi][ni], ah, bh[ni][0], bh[ni][1]);
            }
        }
        __syncthreads();
    }

    // epilogue
#pragma unroll
    for (int mi = 0; mi < 4; mi++) {
#pragma unroll
        for (int ni = 0; ni < 4; ni++) {
            int lc = warp_n + ni * 8 + tg * 2;
            float bx = bias_s[lc], by = bias_s[lc + 1];
            int gc  = n0 + lc;
            int gr0 = row0 + warp_m + mi * 16 + g;
            int gr1 = gr0 + 8;
            float2 v0, v1;
            v0.x = acc[mi][ni][0] + bx; v0.y = acc[mi][ni][1] + by;
            v1.x = acc[mi][ni][2] + bx; v1.y = acc[mi][ni][3] + by;
            if (RELU) {
                v0.x = fmaxf(v0.x, 0.f); v0.y = fmaxf(v0.y, 0.f);
                v1.x = fmaxf(v1.x, 0.f); v1.y = fmaxf(v1.y, 0.f);
            }
            if (OUT_FP16) {
                if (gr0 < N_NODES) g_feat[(size_t)gr0 * 128 + (gc >> 1)] = pack_f2h2(v0.x, v0.y);
                if (gr1 < N_NODES) g_feat[(size_t)gr1 * 128 + (gc >> 1)] = pack_f2h2(v1.x, v1.y);
            } else {
                if (gr0 < N_NODES) *(float2*)&out_param[(size_t)gr0 * D + gc] = v0;
                if (gr1 < N_NODES) *(float2*)&out_param[(size_t)gr1 * D + gc] = v1;
            }
        }
    }
}

// ---------------- launch ----------------
extern "C" void kernel_launch(void* const* d_in, const int* in_sizes, int n_in,
                              void* d_out, int out_size)
{
    const float* x   = (const float*)d_in[0];
    const int*   ei  = (const int*)d_in[1];     // JAX randint -> int32 (x64 disabled)
    const float* W1l = (const float*)d_in[2];
    const float* b1  = (const float*)d_in[3];
    const float* W1r = (const float*)d_in[4];
    const float* W2l = (const float*)d_in[5];
    const float* b2  = (const float*)d_in[6];
    const float* W2r = (const float*)d_in[7];
    float*       out = (float*)d_out;

    int E = in_sizes[1] / 2;
    if (E > E_MAX) E = E_MAX;

    cudaFuncSetAttribute(gemm_f16_kernel<true, true>,
                         cudaFuncAttributeMaxDynamicSharedMemorySize, SM_DYN);
    cudaFuncSetAttribute(gemm_f16_kernel<false, false>,
                         cudaFuncAttributeMaxDynamicSharedMemorySize, SM_DYN);

    int nb_count = (E + 255) / 256;
    int nb_conv  = (N_NODES * 128 + 255) / 256;

    // 0: degree count + x->fp16
    prep_kernel<<<nb_count + nb_conv, 256>>>(ei, x, E, nb_count);
    // 1: scan (re-zeros deg for next replay)
    scanall_kernel<<<1, 1024>>>(E);
    // 2: CSR scatter
    scatter_kernel<<<nb_count, 256>>>(ei, E);
    // 3: weight conversion
    convert_w_kernel<<<512, 256>>>(W1l, W1r, W2l, W2r);
    // 4: layer-1 aggregation
    aggregate_kernel<<<N_NODES / 4, 128>>>();

    dim3 ggrid((N_PAD + 255) / 256, 2);   // 196 x 2
    // 5: layer-1 GEMM -> g_feat (profiled slot)
    gemm_f16_kernel<true, true><<<ggrid, 512, SM_DYN>>>(0, b1, nullptr);
    // 6: layer-2 aggregation
    aggregate_kernel<<<N_NODES / 4, 128>>>();
    // 7: layer-2 GEMM -> out (f32)
    gemm_f16_kernel<false, false><<<ggrid, 512, SM_DYN>>>(1, b2, out);
}